// round 16
// baseline (speedup 1.0000x reference)
#include <cuda_runtime.h>
#include <cuda_bf16.h>
#include <math.h>
#include <stdint.h>

#define NT 20000
#define NC 80000
#define NALL 100000
#define HID 128
#define NHD 8
#define EDG 500000
#define SCALE 0.25f

typedef __nv_bfloat16 bf16;
typedef __nv_bfloat162 bf162;

// ---------------- scratch ----------------
__device__ bf16  g_qb[(size_t)NALL * HID];
__device__ bf16  g_kv[(size_t)NALL * 2 * HID];   // interleaved: row r = [k(128) | v(128)]
__device__ float g_o [(size_t)NALL * HID];
__device__ int   g_cnt  [NALL + 1];
__device__ int   g_start[NALL];
__device__ int   g_fill [NALL];
__device__ int   g_sorted[2 * EDG];

// ---------------- GEMM helpers ----------------
__device__ __forceinline__ float gelu_exact(float x)
{
    return 0.5f * x * (1.0f + erff(x * 0.70710678118654752f));
}

__device__ __forceinline__ void mma_tf32(float c[4], uint32_t a0, uint32_t a1,
                                         uint32_t a2, uint32_t a3,
                                         uint32_t b0, uint32_t b1)
{
    asm volatile(
        "mma.sync.aligned.m16n8k8.row.col.f32.tf32.tf32.f32 "
        "{%0,%1,%2,%3}, {%4,%5,%6,%7}, {%8,%9}, {%0,%1,%2,%3};"
        : "+f"(c[0]), "+f"(c[1]), "+f"(c[2]), "+f"(c[3])
        : "r"(a0), "r"(a1), "r"(a2), "r"(a3), "r"(b0), "r"(b1));
}

__device__ __forceinline__ void cp16(uint32_t dst, const void* src, bool pred)
{
    asm volatile("cp.async.cg.shared.global [%0], [%1], 16, %2;\n"
                 :: "r"(dst), "l"(src), "r"(pred ? 16 : 0));
}
__device__ __forceinline__ void cp_commit() { asm volatile("cp.async.commit_group;\n"); }
__device__ __forceinline__ void cp_wait1()  { asm volatile("cp.async.wait_group 1;\n"); }
__device__ __forceinline__ void cp_wait0()  { asm volatile("cp.async.wait_group 0;\n"); }

__device__ __forceinline__ void store2s(bf16* C, size_t idx, float a, float b)
{
    *(bf162*)(C + idx) = __floats2bfloat162_rn(a, b);
}

template<int MODE>
__device__ __forceinline__ void chunk_mma(float acc[16][4],
                                          const float* __restrict__ Ab, int astr,
                                          const float* __restrict__ Wb,
                                          int ar, int lane,
                                          const float* lng_s, const float* lnb_s,
                                          float m0, float rs0, float m1, float rs1)
{
    #pragma unroll
    for (int kk = 0; kk < 32; kk += 8) {
        const int ac = kk + (lane & 3);
        float ra0 = Ab[ar * astr + ac];
        float ra1 = Ab[(ar + 8) * astr + ac];
        float ra2 = Ab[ar * astr + ac + 4];
        float ra3 = Ab[(ar + 8) * astr + ac + 4];
        if (MODE == 1) {
            float g0 = lng_s[ac], b0 = lnb_s[ac];
            float g4 = lng_s[ac + 4], b4 = lnb_s[ac + 4];
            ra0 = (ra0 - m0) * rs0 * g0 + b0;
            ra1 = (ra1 - m1) * rs1 * g0 + b0;
            ra2 = (ra2 - m0) * rs0 * g4 + b4;
            ra3 = (ra3 - m1) * rs1 * g4 + b4;
        }
        uint32_t a0 = __float_as_uint(ra0), a1 = __float_as_uint(ra1);
        uint32_t a2 = __float_as_uint(ra2), a3 = __float_as_uint(ra3);
        const int br = kk + (lane & 3);
        const int bc = lane >> 2;
        #pragma unroll
        for (int n = 0; n < 16; n++) {
            uint32_t b0 = __float_as_uint(Wb[br * 136 + n * 8 + bc]);
            uint32_t b1 = __float_as_uint(Wb[(br + 4) * 136 + n * 8 + bc]);
            mma_tf32(acc[n], a0, a1, a2, a3, b0, b1);
        }
    }
}

// ============ fused LN1 + QKV GEMM, weight split across blockIdx.y ============
#define QA_STR 132
#define QA_SZ  (128 * QA_STR)
#define QW_STG (32 * 136)
#define QKV_SMEM ((QA_SZ + 2 * QW_STG) * sizeof(float))

__global__ __launch_bounds__(256) void qkv_kernel(const float* __restrict__ A,
                                                  const float* __restrict__ lng,
                                                  const float* __restrict__ lnb,
                                                  const float* __restrict__ Wq,
                                                  const float* __restrict__ Wk,
                                                  const float* __restrict__ Wv,
                                                  const float* __restrict__ bq,
                                                  const float* __restrict__ bk,
                                                  const float* __restrict__ bv,
                                                  bf16* __restrict__ Oq,
                                                  bf16* __restrict__ Okv, int M)
{
    extern __shared__ float smem[];
    float* As = smem;
    float* Ws = smem + QA_SZ;

    const int w = blockIdx.y;                     // 0=Q, 1=K, 2=V
    const float* W    = (w == 0) ? Wq : (w == 1) ? Wk : Wv;
    const float* bias = (w == 0) ? bq : (w == 1) ? bk : bv;

    const int tid  = threadIdx.x;
    const int warp = tid >> 5;
    const int lane = tid & 31;
    const int r0   = blockIdx.x * 128;
    const uint32_t smem_base = (uint32_t)__cvta_generic_to_shared(smem);

    auto stageW = [&](int s, int k0) {
        #pragma unroll
        for (int i = 0; i < 4; i++) {
            int lin = tid + i * 256;
            int kr  = lin >> 5;
            int c4  = lin & 31;
            uint32_t dst = smem_base + (uint32_t)((QA_SZ + s * QW_STG + kr * 136 + c4 * 4) * 4);
            cp16(dst, W + (size_t)(k0 + kr) * 128 + c4 * 4, true);
        }
    };

    #pragma unroll
    for (int i = 0; i < 16; i++) {
        int lin = tid + i * 256;
        int r   = lin >> 5;
        int c4  = lin & 31;
        uint32_t dst = smem_base + (uint32_t)((r * QA_STR + c4 * 4) * 4);
        cp16(dst, A + (size_t)(r0 + r) * 128 + c4 * 4, r0 + r < M);
    }
    stageW(0, 0);
    cp_commit();
    cp_wait0();
    __syncthreads();

    // fused LN over staged A tile (redundant per w — cheap, A is L2-resident)
    {
        int r = tid >> 1, half = tid & 1;
        float* rowp = As + r * QA_STR + half * 64;
        float s = 0.f, ss = 0.f;
        #pragma unroll
        for (int j = 0; j < 32; j++) {
            float2 v = *(float2*)(rowp + j * 2);
            s += v.x + v.y; ss += v.x * v.x + v.y * v.y;
        }
        s  += __shfl_xor_sync(0xffffffffu, s, 1);
        ss += __shfl_xor_sync(0xffffffffu, ss, 1);
        float mean = s * (1.0f / HID);
        float var  = ss * (1.0f / HID) - mean * mean;
        float rstd = rsqrtf(var + 1e-5f);
        const float* gp = lng + half * 64;
        const float* bb = lnb + half * 64;
        #pragma unroll
        for (int j = 0; j < 32; j++) {
            float2 v  = *(float2*)(rowp + j * 2);
            float2 gv = *(const float2*)(gp + j * 2);
            float2 bv = *(const float2*)(bb + j * 2);
            v.x = (v.x - mean) * rstd * gv.x + bv.x;
            v.y = (v.y - mean) * rstd * gv.y + bv.y;
            *(float2*)(rowp + j * 2) = v;
        }
    }
    __syncthreads();

    const int ar = warp * 16 + (lane >> 2);
    float acc[16][4];
    #pragma unroll
    for (int n = 0; n < 16; n++)
        #pragma unroll
        for (int j = 0; j < 4; j++) acc[n][j] = 0.0f;

    #pragma unroll
    for (int kc = 0; kc < 4; kc++) {
        if (kc < 3) stageW((kc + 1) & 1, (kc + 1) * 32);
        cp_commit();
        cp_wait1();
        __syncthreads();
        chunk_mma<0>(acc, As + kc * 32, QA_STR, Ws + (kc & 1) * QW_STG,
                     ar, lane, nullptr, nullptr, 0.f, 0.f, 0.f, 0.f);
        __syncthreads();
    }

    const int r  = r0 + ar;
    const int cb = 2 * (lane & 3);
    // output: w==0 -> Q (stride 128); w==1 -> KV k-half; w==2 -> KV v-half
    bf16* C = (w == 0) ? Oq : Okv;
    const size_t stride = (w == 0) ? 128 : 256;
    const size_t off    = (w == 2) ? 128 : 0;
    #pragma unroll
    for (int n = 0; n < 16; n++) {
        const int col = n * 8 + cb;
        float2 bb = *(const float2*)(bias + col);
        if (r < M)     store2s(C, (size_t)r * stride + off + col,
                               acc[n][0] + bb.x, acc[n][1] + bb.y);
        if (r + 8 < M) store2s(C, (size_t)(r + 8) * stride + off + col,
                               acc[n][2] + bb.x, acc[n][3] + bb.y);
    }
}

// ============ tail mega-kernel ============
#define TL_STR 132
#define TL_SZ  (128 * TL_STR)
#define TAIL_SMEM ((2 * TL_SZ + 2 * QW_STG + 512) * sizeof(float))

__global__ __launch_bounds__(256) void tail_kernel(const float* __restrict__ Oin,
                                                   const float* __restrict__ x_all,
                                                   const float* __restrict__ Wo,
                                                   const float* __restrict__ bo,
                                                   const float* __restrict__ ln2g,
                                                   const float* __restrict__ ln2b,
                                                   const float* __restrict__ W1,
                                                   const float* __restrict__ b1,
                                                   const float* __restrict__ W2,
                                                   const float* __restrict__ b2,
                                                   float* __restrict__ out, int M)
{
    extern __shared__ float smem[];
    float* Xs      = smem;
    float* Bs      = smem + TL_SZ;
    float* Ws      = smem + 2 * TL_SZ;
    float* sm_mean = Ws + 2 * QW_STG;
    float* sm_rstd = sm_mean + 128;
    float* lng_s   = sm_rstd + 128;
    float* lnb_s   = lng_s + 128;

    const float* Wp[3] = {Wo, W1, W2};

    const int tid  = threadIdx.x;
    const int warp = tid >> 5;
    const int lane = tid & 31;
    const int r0   = blockIdx.x * 128;
    const uint32_t smem_base = (uint32_t)__cvta_generic_to_shared(smem);

    auto stageW = [&](int s, const float* W, int k0) {
        #pragma unroll
        for (int i = 0; i < 4; i++) {
            int lin = tid + i * 256;
            int kr  = lin >> 5;
            int c4  = lin & 31;
            uint32_t dst = smem_base + (uint32_t)((2 * TL_SZ + s * QW_STG + kr * 136 + c4 * 4) * 4);
            cp16(dst, W + (size_t)(k0 + kr) * 128 + c4 * 4, true);
        }
    };

    #pragma unroll
    for (int i = 0; i < 16; i++) {
        int lin = tid + i * 256;
        int r   = lin >> 5;
        int c4  = lin & 31;
        uint32_t dst = smem_base + (uint32_t)((r * TL_STR + c4 * 4) * 4);
        cp16(dst, Oin + (size_t)(r0 + r) * 128 + c4 * 4, r0 + r < M);
    }
    stageW(0, Wo, 0);
    cp_commit();
    if (tid < 128) {
        lng_s[tid] = ln2g[tid];
        lnb_s[tid] = ln2b[tid];
    }

    const int ar = warp * 16 + (lane >> 2);
    const int cb = 2 * (lane & 3);
    const int rg = r0 + ar;

    float acc[16][4];

    // ---- GEMM 1: o @ Wo ----
    #pragma unroll
    for (int n = 0; n < 16; n++)
        #pragma unroll
        for (int j = 0; j < 4; j++) acc[n][j] = 0.0f;
    #pragma unroll
    for (int kc = 0; kc < 4; kc++) {
        int t = kc;
        int nt = t + 1;
        stageW(nt & 1, Wp[nt >> 2], (nt & 3) * 32);
        cp_commit();
        cp_wait1();
        __syncthreads();
        chunk_mma<0>(acc, Xs + kc * 32, TL_STR, Ws + (t & 1) * QW_STG,
                     ar, lane, nullptr, nullptr, 0.f, 0.f, 0.f, 0.f);
        __syncthreads();
    }
    #pragma unroll
    for (int n = 0; n < 16; n++) {
        const int col = n * 8 + cb;
        float2 bb = *(const float2*)(bo + col);
        float2 xa = make_float2(0.f, 0.f), xb = make_float2(0.f, 0.f);
        if (rg < M)     xa = *(const float2*)(x_all + (size_t)rg * 128 + col);
        if (rg + 8 < M) xb = *(const float2*)(x_all + (size_t)(rg + 8) * 128 + col);
        Xs[ar * TL_STR + col]           = acc[n][0] + bb.x + xa.x;
        Xs[ar * TL_STR + col + 1]       = acc[n][1] + bb.y + xa.y;
        Xs[(ar + 8) * TL_STR + col]     = acc[n][2] + bb.x + xb.x;
        Xs[(ar + 8) * TL_STR + col + 1] = acc[n][3] + bb.y + xb.y;
    }
    __syncthreads();

    {
        int r = tid >> 1, half = tid & 1;
        const float* rowp = Xs + r * TL_STR + half * 64;
        float s = 0.f, ss = 0.f;
        #pragma unroll
        for (int j = 0; j < 32; j++) {
            float2 v = *(const float2*)(rowp + j * 2);
            s += v.x + v.y; ss += v.x * v.x + v.y * v.y;
        }
        s  += __shfl_xor_sync(0xffffffffu, s, 1);
        ss += __shfl_xor_sync(0xffffffffu, ss, 1);
        if (half == 0) {
            float mean = s * (1.0f / HID);
            float var  = ss * (1.0f / HID) - mean * mean;
            sm_mean[r] = mean;
            sm_rstd[r] = rsqrtf(var + 1e-5f);
        }
    }
    __syncthreads();

    // ---- GEMM 2: LN2(x) @ W1 ----
    const float m0  = sm_mean[ar],     rs0 = sm_rstd[ar];
    const float m1  = sm_mean[ar + 8], rs1 = sm_rstd[ar + 8];
    #pragma unroll
    for (int n = 0; n < 16; n++)
        #pragma unroll
        for (int j = 0; j < 4; j++) acc[n][j] = 0.0f;
    #pragma unroll
    for (int kc = 0; kc < 4; kc++) {
        int t = 4 + kc;
        int nt = t + 1;
        stageW(nt & 1, Wp[nt >> 2], (nt & 3) * 32);
        cp_commit();
        cp_wait1();
        __syncthreads();
        chunk_mma<1>(acc, Xs + kc * 32, TL_STR, Ws + (t & 1) * QW_STG,
                     ar, lane, lng_s, lnb_s, m0, rs0, m1, rs1);
        __syncthreads();
    }
    #pragma unroll
    for (int n = 0; n < 16; n++) {
        const int col = n * 8 + cb;
        float2 bb = *(const float2*)(b1 + col);
        Bs[ar * TL_STR + col]           = gelu_exact(acc[n][0] + bb.x);
        Bs[ar * TL_STR + col + 1]       = gelu_exact(acc[n][1] + bb.y);
        Bs[(ar + 8) * TL_STR + col]     = gelu_exact(acc[n][2] + bb.x);
        Bs[(ar + 8) * TL_STR + col + 1] = gelu_exact(acc[n][3] + bb.y);
    }
    __syncthreads();

    // ---- GEMM 3: gelu @ W2 ----
    #pragma unroll
    for (int n = 0; n < 16; n++)
        #pragma unroll
        for (int j = 0; j < 4; j++) acc[n][j] = 0.0f;
    #pragma unroll
    for (int kc = 0; kc < 4; kc++) {
        int t = 8 + kc;
        if (t < 11) {
            int nt = t + 1;
            stageW(nt & 1, Wp[nt >> 2], (nt & 3) * 32);
        }
        cp_commit();
        cp_wait1();
        __syncthreads();
        chunk_mma<0>(acc, Bs + kc * 32, TL_STR, Ws + (t & 1) * QW_STG,
                     ar, lane, nullptr, nullptr, 0.f, 0.f, 0.f, 0.f);
        __syncthreads();
    }
    #pragma unroll
    for (int n = 0; n < 16; n++) {
        const int col = n * 8 + cb;
        float2 bb = *(const float2*)(b2 + col);
        if (rg < M) {
            float2 o;
            o.x = acc[n][0] + bb.x + Xs[ar * TL_STR + col];
            o.y = acc[n][1] + bb.y + Xs[ar * TL_STR + col + 1];
            *(float2*)(out + (size_t)rg * 128 + col) = o;
        }
        if (rg + 8 < M) {
            float2 o;
            o.x = acc[n][2] + bb.x + Xs[(ar + 8) * TL_STR + col];
            o.y = acc[n][3] + bb.y + Xs[(ar + 8) * TL_STR + col + 1];
            *(float2*)(out + (size_t)(rg + 8) * 128 + col) = o;
        }
    }
}

// ================= combined CSR build =================
__global__ __launch_bounds__(256) void hist_kernel(const int* __restrict__ row1,
                                                   const int* __restrict__ row2,
                                                   int* __restrict__ cnt)
{
    int i = blockIdx.x * 256 + threadIdx.x;
    if (i < EDG) {
        atomicAdd(&cnt[row1[i]], 1);
        atomicAdd(&cnt[NT + row2[i]], 1);
    }
}

__global__ __launch_bounds__(256) void scan_kernel(int* __restrict__ cnt,
                                                   int* __restrict__ start,
                                                   int* __restrict__ fill, int n)
{
    __shared__ int wtot[8], woff[8], blk_base;
    int b = blockIdx.x, t = threadIdx.x;
    int lane = t & 31, w = t >> 5;
    int base = b * 1024 + t * 4;
    int v[4], s = 0;
    #pragma unroll
    for (int j = 0; j < 4; j++) {
        v[j] = (base + j < n) ? cnt[base + j] : 0;
        s += v[j];
    }
    int incl = s;
    #pragma unroll
    for (int off = 1; off < 32; off <<= 1) {
        int x = __shfl_up_sync(0xffffffffu, incl, off);
        if (lane >= off) incl += x;
    }
    if (lane == 31) wtot[w] = incl;
    __syncthreads();
    if (t == 0) {
        int a = 0;
        for (int i = 0; i < 8; i++) { woff[i] = a; a += wtot[i]; }
        blk_base = atomicAdd(&cnt[n], a);
    }
    __syncthreads();
    int off = blk_base + woff[w] + incl - s;
    #pragma unroll
    for (int j = 0; j < 4; j++) {
        if (base + j < n) { start[base + j] = off; fill[base + j] = off; }
        off += v[j];
    }
}

__global__ __launch_bounds__(256) void scatter_kernel(const int* __restrict__ row1,
                                                      const int* __restrict__ row2,
                                                      int* __restrict__ fill,
                                                      int* __restrict__ sorted)
{
    int i = blockIdx.x * 256 + threadIdx.x;
    if (i < EDG) {
        int p1 = atomicAdd(&fill[row1[i]], 1);
        sorted[p1] = i;
        int p2 = atomicAdd(&fill[NT + row2[i]], 1);
        sorted[p2] = i;
    }
}

// ============ combined CSR edge aggregate: warp per row, unroll-4, interleaved KV ====
__global__ __launch_bounds__(256) void edge_agg_kernel(const bf16* __restrict__ Q,
                                                       const bf16* __restrict__ KV,
                                                       const int* __restrict__ col1,
                                                       const int* __restrict__ col2,
                                                       const float* __restrict__ bias1,
                                                       const float* __restrict__ bias2,
                                                       const int* __restrict__ start,
                                                       const int* __restrict__ cnt,
                                                       const int* __restrict__ sorted,
                                                       float* __restrict__ O)
{
    int r = blockIdx.x * 8 + (threadIdx.x >> 5);
    if (r >= NALL) return;
    int lane = threadIdx.x & 31;
    int h = lane >> 2;

    const bool dir1 = (r < NT);
    const int* col    = dir1 ? col1  : col2;
    const float* bias = dir1 ? bias1 : bias2;
    const int koff  = dir1 ? NT : 0;
    const int orow  = dir1 ? (NC + r) : (r - NT);

    uint2 qraw = *((const uint2*)(Q + (size_t)r * HID) + lane);
    float2 qa = __bfloat1622float2(*(bf162*)&qraw.x);
    float2 qb = __bfloat1622float2(*(bf162*)&qraw.y);

    float a0 = 0.f, a1 = 0.f, a2 = 0.f, a3 = 0.f, z = 0.f;

    int i = start[r];
    const int e_end = i + cnt[r];

    for (; i + 4 <= e_end; i += 4) {
        int e0 = __ldg(&sorted[i]);
        int e1 = __ldg(&sorted[i + 1]);
        int e2 = __ldg(&sorted[i + 2]);
        int e3 = __ldg(&sorted[i + 3]);
        int c0 = __ldg(&col[e0]) + koff;
        int c1 = __ldg(&col[e1]) + koff;
        int c2 = __ldg(&col[e2]) + koff;
        int c3 = __ldg(&col[e3]) + koff;
        const uint2* p0 = (const uint2*)(KV + (size_t)c0 * 256) + lane;
        const uint2* p1 = (const uint2*)(KV + (size_t)c1 * 256) + lane;
        const uint2* p2 = (const uint2*)(KV + (size_t)c2 * 256) + lane;
        const uint2* p3 = (const uint2*)(KV + (size_t)c3 * 256) + lane;
        uint2 k0 = p0[0],  k1 = p1[0],  k2 = p2[0],  k3 = p3[0];
        uint2 v0 = p0[32], v1 = p1[32], v2 = p2[32], v3 = p3[32];
        float b0v = __ldg(&bias[(size_t)e0 * NHD + h]);
        float b1v = __ldg(&bias[(size_t)e1 * NHD + h]);
        float b2v = __ldg(&bias[(size_t)e2 * NHD + h]);
        float b3v = __ldg(&bias[(size_t)e3 * NHD + h]);

        float2 ka, kb;
        ka = __bfloat1622float2(*(bf162*)&k0.x); kb = __bfloat1622float2(*(bf162*)&k0.y);
        float d0 = qa.x * ka.x + qa.y * ka.y + qb.x * kb.x + qb.y * kb.y;
        ka = __bfloat1622float2(*(bf162*)&k1.x); kb = __bfloat1622float2(*(bf162*)&k1.y);
        float d1 = qa.x * ka.x + qa.y * ka.y + qb.x * kb.x + qb.y * kb.y;
        ka = __bfloat1622float2(*(bf162*)&k2.x); kb = __bfloat1622float2(*(bf162*)&k2.y);
        float d2 = qa.x * ka.x + qa.y * ka.y + qb.x * kb.x + qb.y * kb.y;
        ka = __bfloat1622float2(*(bf162*)&k3.x); kb = __bfloat1622float2(*(bf162*)&k3.y);
        float d3 = qa.x * ka.x + qa.y * ka.y + qb.x * kb.x + qb.y * kb.y;

        d0 += __shfl_xor_sync(0xffffffffu, d0, 1);
        d1 += __shfl_xor_sync(0xffffffffu, d1, 1);
        d2 += __shfl_xor_sync(0xffffffffu, d2, 1);
        d3 += __shfl_xor_sync(0xffffffffu, d3, 1);
        d0 += __shfl_xor_sync(0xffffffffu, d0, 2);
        d1 += __shfl_xor_sync(0xffffffffu, d1, 2);
        d2 += __shfl_xor_sync(0xffffffffu, d2, 2);
        d3 += __shfl_xor_sync(0xffffffffu, d3, 2);

        float ex0 = __expf(d0 * SCALE + b0v);
        float ex1 = __expf(d1 * SCALE + b1v);
        float ex2 = __expf(d2 * SCALE + b2v);
        float ex3 = __expf(d3 * SCALE + b3v);
        z += (ex0 + ex1) + (ex2 + ex3);

        float2 va, vb;
        va = __bfloat1622float2(*(bf162*)&v0.x); vb = __bfloat1622float2(*(bf162*)&v0.y);
        a0 += ex0 * va.x; a1 += ex0 * va.y; a2 += ex0 * vb.x; a3 += ex0 * vb.y;
        va = __bfloat1622float2(*(bf162*)&v1.x); vb = __bfloat1622float2(*(bf162*)&v1.y);
        a0 += ex1 * va.x; a1 += ex1 * va.y; a2 += ex1 * vb.x; a3 += ex1 * vb.y;
        va = __bfloat1622float2(*(bf162*)&v2.x); vb = __bfloat1622float2(*(bf162*)&v2.y);
        a0 += ex2 * va.x; a1 += ex2 * va.y; a2 += ex2 * vb.x; a3 += ex2 * vb.y;
        va = __bfloat1622float2(*(bf162*)&v3.x); vb = __bfloat1622float2(*(bf162*)&v3.y);
        a0 += ex3 * va.x; a1 += ex3 * va.y; a2 += ex3 * vb.x; a3 += ex3 * vb.y;
    }
    for (; i < e_end; i++) {
        int e0 = __ldg(&sorted[i]);
        int c0 = __ldg(&col[e0]) + koff;
        const uint2* p0 = (const uint2*)(KV + (size_t)c0 * 256) + lane;
        uint2 k0 = p0[0];
        uint2 v0 = p0[32];
        float2 ka = __bfloat1622float2(*(bf162*)&k0.x);
        float2 kb = __bfloat1622float2(*(bf162*)&k0.y);
        float d0 = qa.x * ka.x + qa.y * ka.y + qb.x * kb.x + qb.y * kb.y;
        d0 += __shfl_xor_sync(0xffffffffu, d0, 1);
        d0 += __shfl_xor_sync(0xffffffffu, d0, 2);
        float ex0 = __expf(d0 * SCALE + __ldg(&bias[(size_t)e0 * NHD + h]));
        z += ex0;
        float2 va = __bfloat1622float2(*(bf162*)&v0.x);
        float2 vb = __bfloat1622float2(*(bf162*)&v0.y);
        a0 += ex0 * va.x; a1 += ex0 * va.y;
        a2 += ex0 * vb.x; a3 += ex0 * vb.y;
    }

    float rz = 1.0f / (z + 1e-16f);
    *(float4*)(O + (size_t)orow * HID + lane * 4) =
        make_float4(a0 * rz, a1 * rz, a2 * rz, a3 * rz);
}

// ---------------- host ----------------
extern "C" void kernel_launch(void* const* d_in, const int* in_sizes, int n_in,
                              void* d_out, int out_size)
{
    const float* x_all    = (const float*)d_in[0];
    const float* bias_c2t = (const float*)d_in[1];
    const float* bias_t2c = (const float*)d_in[2];
    const int*   c2t_row  = (const int*)d_in[3];
    const int*   c2t_col  = (const int*)d_in[4];
    const int*   t2c_row  = (const int*)d_in[5];
    const int*   t2c_col  = (const int*)d_in[6];
    const float* ln1_g    = (const float*)d_in[7];
    const float* ln1_b    = (const float*)d_in[8];
    const float* Wq = (const float*)d_in[9];   const float* bq = (const float*)d_in[10];
    const float* Wk = (const float*)d_in[11];  const float* bk = (const float*)d_in[12];
    const float* Wv = (const float*)d_in[13];  const float* bv = (const float*)d_in[14];
    const float* Wo = (const float*)d_in[15];  const float* bo = (const float*)d_in[16];
    const float* ln2_g = (const float*)d_in[17];
    const float* ln2_b = (const float*)d_in[18];
    const float* W1 = (const float*)d_in[19];  const float* b1 = (const float*)d_in[20];
    const float* W2 = (const float*)d_in[21];  const float* b2 = (const float*)d_in[22];
    float* out = (float*)d_out;

    float *o;
    bf16 *qb, *kv;
    int *cnt, *start, *fill, *sorted;
    cudaGetSymbolAddress((void**)&qb, g_qb);
    cudaGetSymbolAddress((void**)&kv, g_kv);
    cudaGetSymbolAddress((void**)&o,  g_o);
    cudaGetSymbolAddress((void**)&cnt,    g_cnt);
    cudaGetSymbolAddress((void**)&start,  g_start);
    cudaGetSymbolAddress((void**)&fill,   g_fill);
    cudaGetSymbolAddress((void**)&sorted, g_sorted);

    cudaFuncSetAttribute(qkv_kernel,
                         cudaFuncAttributeMaxDynamicSharedMemorySize, QKV_SMEM);
    cudaFuncSetAttribute(tail_kernel,
                         cudaFuncAttributeMaxDynamicSharedMemorySize, TAIL_SMEM);

    const int gemmGrid = (NALL + 127) / 128;
    const int eGrid    = (EDG + 255) / 256;
    const int nb       = (NALL + 1023) / 1024;

    // CSR build first (independent of qkv)
    cudaMemsetAsync(cnt, 0, (NALL + 1) * sizeof(int), 0);
    hist_kernel<<<eGrid, 256>>>(c2t_row, t2c_row, cnt);
    scan_kernel<<<nb, 256>>>(cnt, start, fill, NALL);
    scatter_kernel<<<eGrid, 256>>>(c2t_row, t2c_row, fill, sorted);

    // LN1 + QKV, weights split across blockIdx.y
    qkv_kernel<<<dim3(gemmGrid, 3), 256, QKV_SMEM>>>(x_all, ln1_g, ln1_b, Wq, Wk, Wv,
                                                     bq, bk, bv, qb, kv, NALL);

    edge_agg_kernel<<<(NALL + 7) / 8, 256>>>(qb, kv, c2t_col, t2c_col,
                                             bias_c2t, bias_t2c,
                                             start, cnt, sorted, o);

    tail_kernel<<<gemmGrid, 256, TAIL_SMEM>>>(o, x_all, Wo, bo, ln2_g, ln2_b,
                                              W1, b1, W2, b2, out, NALL);
}

// round 17
// speedup vs baseline: 1.1216x; 1.1216x over previous
#include <cuda_runtime.h>
#include <cuda_bf16.h>
#include <math.h>
#include <stdint.h>

#define NT 20000
#define NC 80000
#define NALL 100000
#define HID 128
#define NHD 8
#define EDG 500000
#define SCALE 0.25f

typedef __nv_bfloat16 bf16;
typedef __nv_bfloat162 bf162;

// ---------------- scratch ----------------
__device__ bf16  g_qb[(size_t)NALL * HID];
__device__ bf16  g_kv[(size_t)NALL * 2 * HID];   // interleaved: row r = [k(128) | v(128)]
__device__ float g_o [(size_t)NALL * HID];
__device__ bf16  g_wb[3 * 128 * 136];            // Wq/Wk/Wv transposed [n][k] bf16
__device__ int   g_cnt  [NALL + 1];
__device__ int   g_start[NALL];
__device__ int   g_fill [NALL];
__device__ int   g_sorted[2 * EDG];

// ---------------- helpers ----------------
__device__ __forceinline__ float gelu_exact(float x)
{
    return 0.5f * x * (1.0f + erff(x * 0.70710678118654752f));
}

__device__ __forceinline__ void mma_tf32(float c[4], uint32_t a0, uint32_t a1,
                                         uint32_t a2, uint32_t a3,
                                         uint32_t b0, uint32_t b1)
{
    asm volatile(
        "mma.sync.aligned.m16n8k8.row.col.f32.tf32.tf32.f32 "
        "{%0,%1,%2,%3}, {%4,%5,%6,%7}, {%8,%9}, {%0,%1,%2,%3};"
        : "+f"(c[0]), "+f"(c[1]), "+f"(c[2]), "+f"(c[3])
        : "r"(a0), "r"(a1), "r"(a2), "r"(a3), "r"(b0), "r"(b1));
}

__device__ __forceinline__ void mma_bf16(float c[4], uint32_t a0, uint32_t a1,
                                         uint32_t a2, uint32_t a3,
                                         uint32_t b0, uint32_t b1)
{
    asm volatile(
        "mma.sync.aligned.m16n8k16.row.col.f32.bf16.bf16.f32 "
        "{%0,%1,%2,%3}, {%4,%5,%6,%7}, {%8,%9}, {%0,%1,%2,%3};"
        : "+f"(c[0]), "+f"(c[1]), "+f"(c[2]), "+f"(c[3])
        : "r"(a0), "r"(a1), "r"(a2), "r"(a3), "r"(b0), "r"(b1));
}

__device__ __forceinline__ void cp16(uint32_t dst, const void* src, bool pred)
{
    asm volatile("cp.async.cg.shared.global [%0], [%1], 16, %2;\n"
                 :: "r"(dst), "l"(src), "r"(pred ? 16 : 0));
}
__device__ __forceinline__ void cp_commit() { asm volatile("cp.async.commit_group;\n"); }
__device__ __forceinline__ void cp_wait1()  { asm volatile("cp.async.wait_group 1;\n"); }
__device__ __forceinline__ void cp_wait0()  { asm volatile("cp.async.wait_group 0;\n"); }

__device__ __forceinline__ void store2s(bf16* C, size_t idx, float a, float b)
{
    *(bf162*)(C + idx) = __floats2bfloat162_rn(a, b);
}

template<int MODE>
__device__ __forceinline__ void chunk_mma(float acc[16][4],
                                          const float* __restrict__ Ab, int astr,
                                          const float* __restrict__ Wb,
                                          int ar, int lane,
                                          const float* lng_s, const float* lnb_s,
                                          float m0, float rs0, float m1, float rs1)
{
    #pragma unroll
    for (int kk = 0; kk < 32; kk += 8) {
        const int ac = kk + (lane & 3);
        float ra0 = Ab[ar * astr + ac];
        float ra1 = Ab[(ar + 8) * astr + ac];
        float ra2 = Ab[ar * astr + ac + 4];
        float ra3 = Ab[(ar + 8) * astr + ac + 4];
        if (MODE == 1) {
            float g0 = lng_s[ac], b0 = lnb_s[ac];
            float g4 = lng_s[ac + 4], b4 = lnb_s[ac + 4];
            ra0 = (ra0 - m0) * rs0 * g0 + b0;
            ra1 = (ra1 - m1) * rs1 * g0 + b0;
            ra2 = (ra2 - m0) * rs0 * g4 + b4;
            ra3 = (ra3 - m1) * rs1 * g4 + b4;
        }
        uint32_t a0 = __float_as_uint(ra0), a1 = __float_as_uint(ra1);
        uint32_t a2 = __float_as_uint(ra2), a3 = __float_as_uint(ra3);
        const int br = kk + (lane & 3);
        const int bc = lane >> 2;
        #pragma unroll
        for (int n = 0; n < 16; n++) {
            uint32_t b0 = __float_as_uint(Wb[br * 136 + n * 8 + bc]);
            uint32_t b1 = __float_as_uint(Wb[(br + 4) * 136 + n * 8 + bc]);
            mma_tf32(acc[n], a0, a1, a2, a3, b0, b1);
        }
    }
}

// ============ weight prep: Wq/Wk/Wv -> [n][k] bf16 ============
__global__ __launch_bounds__(256) void prep_w_kernel(const float* __restrict__ Wq,
                                                     const float* __restrict__ Wk,
                                                     const float* __restrict__ Wv)
{
    const float* Wp[3] = {Wq, Wk, Wv};
    int w   = blockIdx.y;
    int idx = blockIdx.x * 256 + threadIdx.x;      // 0..16383
    int k = idx >> 7;                              // 0..127
    int n = idx & 127;                             // 0..127 (coalesced read over n)
    g_wb[w * 128 * 136 + n * 136 + k] = __float2bfloat16(Wp[w][k * 128 + n]);
}

// ============ fused LN1 + QKV GEMM, bf16 tensor cores ============
#define ABF_STR 136
#define WBF_STR 40
#define ABF_BYTES (128 * ABF_STR * 2)              // 34816
#define WST_BYTES (128 * WBF_STR * 2)              // 10240 per stage
#define ASCR_FLOATS (32 * 132)
#define QKV_SMEM (ABF_BYTES + 2 * WST_BYTES + ASCR_FLOATS * 4)   // 72192

__global__ __launch_bounds__(256) void qkv_kernel(const float* __restrict__ A,
                                                  const float* __restrict__ lng,
                                                  const float* __restrict__ lnb,
                                                  const float* __restrict__ bq,
                                                  const float* __restrict__ bk,
                                                  const float* __restrict__ bv,
                                                  bf16* __restrict__ Oq,
                                                  bf16* __restrict__ Okv, int M)
{
    extern __shared__ char smem[];
    bf16*  Asb = (bf16*)smem;                                  // [128][136]
    bf16*  Wsb = (bf16*)(smem + ABF_BYTES);                    // [2][128][40]
    float* scr = (float*)(smem + ABF_BYTES + 2 * WST_BYTES);   // [32][132]

    const float* bp[3] = {bq, bk, bv};

    const int tid  = threadIdx.x;
    const int warp = tid >> 5;
    const int lane = tid & 31;
    const int r0   = blockIdx.x * 128;
    const uint32_t smem_base = (uint32_t)__cvta_generic_to_shared(smem);
    const uint32_t scr_base  = smem_base + ABF_BYTES + 2 * WST_BYTES;
    const uint32_t wsb_base  = smem_base + ABF_BYTES;

    // stage chunk t (weight t>>2, k-chunk t&3) into slot s of Wsb
    auto stageW = [&](int s, int t) {
        const bf16* src = g_wb + (t >> 2) * 128 * 136 + (t & 3) * 32;
        #pragma unroll
        for (int i = 0; i < 2; i++) {
            int lin = tid + i * 256;               // 0..511
            int n   = lin >> 2;                    // 0..127
            int seg = lin & 3;                     // 0..3 (8 bf16 each)
            uint32_t dst = wsb_base + (uint32_t)((s * 128 * WBF_STR + n * WBF_STR + seg * 8) * 2);
            cp16(dst, src + (size_t)n * 136 + seg * 8, true);
        }
    };

    // ---- A: stage fp32 in 32-row quarters, LN, convert to bf16 ----
    for (int q = 0; q < 4; q++) {
        #pragma unroll
        for (int i = 0; i < 4; i++) {
            int lin = tid + i * 256;               // 0..1023
            int rl  = lin >> 5;                    // 0..31
            int c4  = lin & 31;                    // 0..31
            uint32_t dst = scr_base + (uint32_t)((rl * 132 + c4 * 4) * 4);
            cp16(dst, A + (size_t)(r0 + q * 32 + rl) * 128 + c4 * 4, r0 + q * 32 + rl < M);
        }
        cp_commit();
        cp_wait0();
        __syncthreads();

        // LN: 8 threads per row (each 16 floats)
        int rl   = tid >> 3;                       // 0..31
        int part = tid & 7;                        // 0..7
        const float* rowp = scr + rl * 132 + part * 16;
        float s = 0.f, ss = 0.f;
        float2 vbuf[8];
        #pragma unroll
        for (int j = 0; j < 8; j++) {
            vbuf[j] = *(const float2*)(rowp + j * 2);
            s += vbuf[j].x + vbuf[j].y;
            ss += vbuf[j].x * vbuf[j].x + vbuf[j].y * vbuf[j].y;
        }
        s  += __shfl_xor_sync(0xffffffffu, s, 1);
        ss += __shfl_xor_sync(0xffffffffu, ss, 1);
        s  += __shfl_xor_sync(0xffffffffu, s, 2);
        ss += __shfl_xor_sync(0xffffffffu, ss, 2);
        s  += __shfl_xor_sync(0xffffffffu, s, 4);
        ss += __shfl_xor_sync(0xffffffffu, ss, 4);
        float mean = s * (1.0f / HID);
        float var  = ss * (1.0f / HID) - mean * mean;
        float rstd = rsqrtf(var + 1e-5f);
        const float* gp = lng + part * 16;
        const float* bb = lnb + part * 16;
        bf16* orow = Asb + (q * 32 + rl) * ABF_STR + part * 16;
        #pragma unroll
        for (int j = 0; j < 8; j++) {
            float2 gv = *(const float2*)(gp + j * 2);
            float2 bv = *(const float2*)(bb + j * 2);
            float x0 = (vbuf[j].x - mean) * rstd * gv.x + bv.x;
            float x1 = (vbuf[j].y - mean) * rstd * gv.y + bv.y;
            *(bf162*)(orow + j * 2) = __floats2bfloat162_rn(x0, x1);
        }
        __syncthreads();
    }

    // ---- GEMM: 3 weights x 4 chunks, double-buffered W stages ----
    stageW(0, 0);
    cp_commit();

    const int ar = warp * 16 + (lane >> 2);
    #pragma unroll
    for (int w = 0; w < 3; w++) {
        float acc[16][4];
        #pragma unroll
        for (int n = 0; n < 16; n++)
            #pragma unroll
            for (int j = 0; j < 4; j++) acc[n][j] = 0.0f;

        #pragma unroll
        for (int kc = 0; kc < 4; kc++) {
            int t = w * 4 + kc;
            if (t < 11) stageW((t + 1) & 1, t + 1);
            cp_commit();
            cp_wait1();
            __syncthreads();

            const bf16* Wc = Wsb + (t & 1) * 128 * WBF_STR;
            const int kg = kc * 32;
            #pragma unroll
            for (int kk = 0; kk < 32; kk += 16) {
                const int acol = kg + kk + 2 * (lane & 3);
                uint32_t a0 = *(const uint32_t*)(Asb + ar * ABF_STR + acol);
                uint32_t a1 = *(const uint32_t*)(Asb + (ar + 8) * ABF_STR + acol);
                uint32_t a2 = *(const uint32_t*)(Asb + ar * ABF_STR + acol + 8);
                uint32_t a3 = *(const uint32_t*)(Asb + (ar + 8) * ABF_STR + acol + 8);
                const int brow = kk + 2 * (lane & 3);
                const int bn   = lane >> 2;
                #pragma unroll
                for (int n = 0; n < 16; n++) {
                    const bf16* bp2 = Wc + (n * 8 + bn) * WBF_STR + brow;
                    uint32_t b0 = *(const uint32_t*)(bp2);
                    uint32_t b1 = *(const uint32_t*)(bp2 + 8);
                    mma_bf16(acc[n], a0, a1, a2, a3, b0, b1);
                }
            }
            __syncthreads();
        }

        const int r  = r0 + ar;
        const int cb = 2 * (lane & 3);
        const float* bias = bp[w];
        bf16* C = (w == 0) ? Oq : Okv;
        const size_t stride = (w == 0) ? 128 : 256;
        const size_t off    = (w == 2) ? 128 : 0;
        #pragma unroll
        for (int n = 0; n < 16; n++) {
            const int col = n * 8 + cb;
            float2 bb = *(const float2*)(bias + col);
            if (r < M)     store2s(C, (size_t)r * stride + off + col,
                                   acc[n][0] + bb.x, acc[n][1] + bb.y);
            if (r + 8 < M) store2s(C, (size_t)(r + 8) * stride + off + col,
                                   acc[n][2] + bb.x, acc[n][3] + bb.y);
        }
    }
}

// ============ tail mega-kernel (unchanged, tf32) ============
#define TL_STR 132
#define TL_SZ  (128 * TL_STR)
#define QW_STG (32 * 136)
#define TAIL_SMEM ((2 * TL_SZ + 2 * QW_STG + 512) * sizeof(float))

__global__ __launch_bounds__(256) void tail_kernel(const float* __restrict__ Oin,
                                                   const float* __restrict__ x_all,
                                                   const float* __restrict__ Wo,
                                                   const float* __restrict__ bo,
                                                   const float* __restrict__ ln2g,
                                                   const float* __restrict__ ln2b,
                                                   const float* __restrict__ W1,
                                                   const float* __restrict__ b1,
                                                   const float* __restrict__ W2,
                                                   const float* __restrict__ b2,
                                                   float* __restrict__ out, int M)
{
    extern __shared__ float smemf[];
    float* Xs      = smemf;
    float* Bs      = smemf + TL_SZ;
    float* Ws      = smemf + 2 * TL_SZ;
    float* sm_mean = Ws + 2 * QW_STG;
    float* sm_rstd = sm_mean + 128;
    float* lng_s   = sm_rstd + 128;
    float* lnb_s   = lng_s + 128;

    const float* Wp[3] = {Wo, W1, W2};

    const int tid  = threadIdx.x;
    const int warp = tid >> 5;
    const int lane = tid & 31;
    const int r0   = blockIdx.x * 128;
    const uint32_t smem_base = (uint32_t)__cvta_generic_to_shared(smemf);

    auto stageW = [&](int s, const float* W, int k0) {
        #pragma unroll
        for (int i = 0; i < 4; i++) {
            int lin = tid + i * 256;
            int kr  = lin >> 5;
            int c4  = lin & 31;
            uint32_t dst = smem_base + (uint32_t)((2 * TL_SZ + s * QW_STG + kr * 136 + c4 * 4) * 4);
            cp16(dst, W + (size_t)(k0 + kr) * 128 + c4 * 4, true);
        }
    };

    #pragma unroll
    for (int i = 0; i < 16; i++) {
        int lin = tid + i * 256;
        int r   = lin >> 5;
        int c4  = lin & 31;
        uint32_t dst = smem_base + (uint32_t)((r * TL_STR + c4 * 4) * 4);
        cp16(dst, Oin + (size_t)(r0 + r) * 128 + c4 * 4, r0 + r < M);
    }
    stageW(0, Wo, 0);
    cp_commit();
    if (tid < 128) {
        lng_s[tid] = ln2g[tid];
        lnb_s[tid] = ln2b[tid];
    }

    const int ar = warp * 16 + (lane >> 2);
    const int cb = 2 * (lane & 3);
    const int rg = r0 + ar;

    float acc[16][4];

    // ---- GEMM 1: o @ Wo ----
    #pragma unroll
    for (int n = 0; n < 16; n++)
        #pragma unroll
        for (int j = 0; j < 4; j++) acc[n][j] = 0.0f;
    #pragma unroll
    for (int kc = 0; kc < 4; kc++) {
        int t = kc;
        int nt = t + 1;
        stageW(nt & 1, Wp[nt >> 2], (nt & 3) * 32);
        cp_commit();
        cp_wait1();
        __syncthreads();
        chunk_mma<0>(acc, Xs + kc * 32, TL_STR, Ws + (t & 1) * QW_STG,
                     ar, lane, nullptr, nullptr, 0.f, 0.f, 0.f, 0.f);
        __syncthreads();
    }
    #pragma unroll
    for (int n = 0; n < 16; n++) {
        const int col = n * 8 + cb;
        float2 bb = *(const float2*)(bo + col);
        float2 xa = make_float2(0.f, 0.f), xb = make_float2(0.f, 0.f);
        if (rg < M)     xa = *(const float2*)(x_all + (size_t)rg * 128 + col);
        if (rg + 8 < M) xb = *(const float2*)(x_all + (size_t)(rg + 8) * 128 + col);
        Xs[ar * TL_STR + col]           = acc[n][0] + bb.x + xa.x;
        Xs[ar * TL_STR + col + 1]       = acc[n][1] + bb.y + xa.y;
        Xs[(ar + 8) * TL_STR + col]     = acc[n][2] + bb.x + xb.x;
        Xs[(ar + 8) * TL_STR + col + 1] = acc[n][3] + bb.y + xb.y;
    }
    __syncthreads();

    {
        int r = tid >> 1, half = tid & 1;
        const float* rowp = Xs + r * TL_STR + half * 64;
        float s = 0.f, ss = 0.f;
        #pragma unroll
        for (int j = 0; j < 32; j++) {
            float2 v = *(const float2*)(rowp + j * 2);
            s += v.x + v.y; ss += v.x * v.x + v.y * v.y;
        }
        s  += __shfl_xor_sync(0xffffffffu, s, 1);
        ss += __shfl_xor_sync(0xffffffffu, ss, 1);
        if (half == 0) {
            float mean = s * (1.0f / HID);
            float var  = ss * (1.0f / HID) - mean * mean;
            sm_mean[r] = mean;
            sm_rstd[r] = rsqrtf(var + 1e-5f);
        }
    }
    __syncthreads();

    // ---- GEMM 2: LN2(x) @ W1 ----
    const float m0  = sm_mean[ar],     rs0 = sm_rstd[ar];
    const float m1  = sm_mean[ar + 8], rs1 = sm_rstd[ar + 8];
    #pragma unroll
    for (int n = 0; n < 16; n++)
        #pragma unroll
        for (int j = 0; j < 4; j++) acc[n][j] = 0.0f;
    #pragma unroll
    for (int kc = 0; kc < 4; kc++) {
        int t = 4 + kc;
        int nt = t + 1;
        stageW(nt & 1, Wp[nt >> 2], (nt & 3) * 32);
        cp_commit();
        cp_wait1();
        __syncthreads();
        chunk_mma<1>(acc, Xs + kc * 32, TL_STR, Ws + (t & 1) * QW_STG,
                     ar, lane, lng_s, lnb_s, m0, rs0, m1, rs1);
        __syncthreads();
    }
    #pragma unroll
    for (int n = 0; n < 16; n++) {
        const int col = n * 8 + cb;
        float2 bb = *(const float2*)(b1 + col);
        Bs[ar * TL_STR + col]           = gelu_exact(acc[n][0] + bb.x);
        Bs[ar * TL_STR + col + 1]       = gelu_exact(acc[n][1] + bb.y);
        Bs[(ar + 8) * TL_STR + col]     = gelu_exact(acc[n][2] + bb.x);
        Bs[(ar + 8) * TL_STR + col + 1] = gelu_exact(acc[n][3] + bb.y);
    }
    __syncthreads();

    // ---- GEMM 3: gelu @ W2 ----
    #pragma unroll
    for (int n = 0; n < 16; n++)
        #pragma unroll
        for (int j = 0; j < 4; j++) acc[n][j] = 0.0f;
    #pragma unroll
    for (int kc = 0; kc < 4; kc++) {
        int t = 8 + kc;
        if (t < 11) {
            int nt = t + 1;
            stageW(nt & 1, Wp[nt >> 2], (nt & 3) * 32);
        }
        cp_commit();
        cp_wait1();
        __syncthreads();
        chunk_mma<0>(acc, Bs + kc * 32, TL_STR, Ws + (t & 1) * QW_STG,
                     ar, lane, nullptr, nullptr, 0.f, 0.f, 0.f, 0.f);
        __syncthreads();
    }
    #pragma unroll
    for (int n = 0; n < 16; n++) {
        const int col = n * 8 + cb;
        float2 bb = *(const float2*)(b2 + col);
        if (rg < M) {
            float2 o;
            o.x = acc[n][0] + bb.x + Xs[ar * TL_STR + col];
            o.y = acc[n][1] + bb.y + Xs[ar * TL_STR + col + 1];
            *(float2*)(out + (size_t)rg * 128 + col) = o;
        }
        if (rg + 8 < M) {
            float2 o;
            o.x = acc[n][2] + bb.x + Xs[(ar + 8) * TL_STR + col];
            o.y = acc[n][3] + bb.y + Xs[(ar + 8) * TL_STR + col + 1];
            *(float2*)(out + (size_t)(rg + 8) * 128 + col) = o;
        }
    }
}

// ================= combined CSR build =================
__global__ __launch_bounds__(256) void hist_kernel(const int* __restrict__ row1,
                                                   const int* __restrict__ row2,
                                                   int* __restrict__ cnt)
{
    int i = blockIdx.x * 256 + threadIdx.x;
    if (i < EDG) {
        atomicAdd(&cnt[row1[i]], 1);
        atomicAdd(&cnt[NT + row2[i]], 1);
    }
}

__global__ __launch_bounds__(256) void scan_kernel(int* __restrict__ cnt,
                                                   int* __restrict__ start,
                                                   int* __restrict__ fill, int n)
{
    __shared__ int wtot[8], woff[8], blk_base;
    int b = blockIdx.x, t = threadIdx.x;
    int lane = t & 31, w = t >> 5;
    int base = b * 1024 + t * 4;
    int v[4], s = 0;
    #pragma unroll
    for (int j = 0; j < 4; j++) {
        v[j] = (base + j < n) ? cnt[base + j] : 0;
        s += v[j];
    }
    int incl = s;
    #pragma unroll
    for (int off = 1; off < 32; off <<= 1) {
        int x = __shfl_up_sync(0xffffffffu, incl, off);
        if (lane >= off) incl += x;
    }
    if (lane == 31) wtot[w] = incl;
    __syncthreads();
    if (t == 0) {
        int a = 0;
        for (int i = 0; i < 8; i++) { woff[i] = a; a += wtot[i]; }
        blk_base = atomicAdd(&cnt[n], a);
    }
    __syncthreads();
    int off = blk_base + woff[w] + incl - s;
    #pragma unroll
    for (int j = 0; j < 4; j++) {
        if (base + j < n) { start[base + j] = off; fill[base + j] = off; }
        off += v[j];
    }
}

__global__ __launch_bounds__(256) void scatter_kernel(const int* __restrict__ row1,
                                                      const int* __restrict__ row2,
                                                      int* __restrict__ fill,
                                                      int* __restrict__ sorted)
{
    int i = blockIdx.x * 256 + threadIdx.x;
    if (i < EDG) {
        int p1 = atomicAdd(&fill[row1[i]], 1);
        sorted[p1] = i;
        int p2 = atomicAdd(&fill[NT + row2[i]], 1);
        sorted[p2] = i;
    }
}

// ============ combined CSR edge aggregate (unchanged) ============
__global__ __launch_bounds__(256) void edge_agg_kernel(const bf16* __restrict__ Q,
                                                       const bf16* __restrict__ KV,
                                                       const int* __restrict__ col1,
                                                       const int* __restrict__ col2,
                                                       const float* __restrict__ bias1,
                                                       const float* __restrict__ bias2,
                                                       const int* __restrict__ start,
                                                       const int* __restrict__ cnt,
                                                       const int* __restrict__ sorted,
                                                       float* __restrict__ O)
{
    int r = blockIdx.x * 8 + (threadIdx.x >> 5);
    if (r >= NALL) return;
    int lane = threadIdx.x & 31;
    int h = lane >> 2;

    const bool dir1 = (r < NT);
    const int* col    = dir1 ? col1  : col2;
    const float* bias = dir1 ? bias1 : bias2;
    const int koff  = dir1 ? NT : 0;
    const int orow  = dir1 ? (NC + r) : (r - NT);

    uint2 qraw = *((const uint2*)(Q + (size_t)r * HID) + lane);
    float2 qa = __bfloat1622float2(*(bf162*)&qraw.x);
    float2 qb = __bfloat1622float2(*(bf162*)&qraw.y);

    float a0 = 0.f, a1 = 0.f, a2 = 0.f, a3 = 0.f, z = 0.f;

    int i = start[r];
    const int e_end = i + cnt[r];

    for (; i + 4 <= e_end; i += 4) {
        int e0 = __ldg(&sorted[i]);
        int e1 = __ldg(&sorted[i + 1]);
        int e2 = __ldg(&sorted[i + 2]);
        int e3 = __ldg(&sorted[i + 3]);
        int c0 = __ldg(&col[e0]) + koff;
        int c1 = __ldg(&col[e1]) + koff;
        int c2 = __ldg(&col[e2]) + koff;
        int c3 = __ldg(&col[e3]) + koff;
        const uint2* p0 = (const uint2*)(KV + (size_t)c0 * 256) + lane;
        const uint2* p1 = (const uint2*)(KV + (size_t)c1 * 256) + lane;
        const uint2* p2 = (const uint2*)(KV + (size_t)c2 * 256) + lane;
        const uint2* p3 = (const uint2*)(KV + (size_t)c3 * 256) + lane;
        uint2 k0 = p0[0],  k1 = p1[0],  k2 = p2[0],  k3 = p3[0];
        uint2 v0 = p0[32], v1 = p1[32], v2 = p2[32], v3 = p3[32];
        float b0v = __ldg(&bias[(size_t)e0 * NHD + h]);
        float b1v = __ldg(&bias[(size_t)e1 * NHD + h]);
        float b2v = __ldg(&bias[(size_t)e2 * NHD + h]);
        float b3v = __ldg(&bias[(size_t)e3 * NHD + h]);

        float2 ka, kb;
        ka = __bfloat1622float2(*(bf162*)&k0.x); kb = __bfloat1622float2(*(bf162*)&k0.y);
        float d0 = qa.x * ka.x + qa.y * ka.y + qb.x * kb.x + qb.y * kb.y;
        ka = __bfloat1622float2(*(bf162*)&k1.x); kb = __bfloat1622float2(*(bf162*)&k1.y);
        float d1 = qa.x * ka.x + qa.y * ka.y + qb.x * kb.x + qb.y * kb.y;
        ka = __bfloat1622float2(*(bf162*)&k2.x); kb = __bfloat1622float2(*(bf162*)&k2.y);
        float d2 = qa.x * ka.x + qa.y * ka.y + qb.x * kb.x + qb.y * kb.y;
        ka = __bfloat1622float2(*(bf162*)&k3.x); kb = __bfloat1622float2(*(bf162*)&k3.y);
        float d3 = qa.x * ka.x + qa.y * ka.y + qb.x * kb.x + qb.y * kb.y;

        d0 += __shfl_xor_sync(0xffffffffu, d0, 1);
        d1 += __shfl_xor_sync(0xffffffffu, d1, 1);
        d2 += __shfl_xor_sync(0xffffffffu, d2, 1);
        d3 += __shfl_xor_sync(0xffffffffu, d3, 1);
        d0 += __shfl_xor_sync(0xffffffffu, d0, 2);
        d1 += __shfl_xor_sync(0xffffffffu, d1, 2);
        d2 += __shfl_xor_sync(0xffffffffu, d2, 2);
        d3 += __shfl_xor_sync(0xffffffffu, d3, 2);

        float ex0 = __expf(d0 * SCALE + b0v);
        float ex1 = __expf(d1 * SCALE + b1v);
        float ex2 = __expf(d2 * SCALE + b2v);
        float ex3 = __expf(d3 * SCALE + b3v);
        z += (ex0 + ex1) + (ex2 + ex3);

        float2 va, vb;
        va = __bfloat1622float2(*(bf162*)&v0.x); vb = __bfloat1622float2(*(bf162*)&v0.y);
        a0 += ex0 * va.x; a1 += ex0 * va.y; a2 += ex0 * vb.x; a3 += ex0 * vb.y;
        va = __bfloat1622float2(*(bf162*)&v1.x); vb = __bfloat1622float2(*(bf162*)&v1.y);
        a0 += ex1 * va.x; a1 += ex1 * va.y; a2 += ex1 * vb.x; a3 += ex1 * vb.y;
        va = __bfloat1622float2(*(bf162*)&v2.x); vb = __bfloat1622float2(*(bf162*)&v2.y);
        a0 += ex2 * va.x; a1 += ex2 * va.y; a2 += ex2 * vb.x; a3 += ex2 * vb.y;
        va = __bfloat1622float2(*(bf162*)&v3.x); vb = __bfloat1622float2(*(bf162*)&v3.y);
        a0 += ex3 * va.x; a1 += ex3 * va.y; a2 += ex3 * vb.x; a3 += ex3 * vb.y;
    }
    for (; i < e_end; i++) {
        int e0 = __ldg(&sorted[i]);
        int c0 = __ldg(&col[e0]) + koff;
        const uint2* p0 = (const uint2*)(KV + (size_t)c0 * 256) + lane;
        uint2 k0 = p0[0];
        uint2 v0 = p0[32];
        float2 ka = __bfloat1622float2(*(bf162*)&k0.x);
        float2 kb = __bfloat1622float2(*(bf162*)&k0.y);
        float d0 = qa.x * ka.x + qa.y * ka.y + qb.x * kb.x + qb.y * kb.y;
        d0 += __shfl_xor_sync(0xffffffffu, d0, 1);
        d0 += __shfl_xor_sync(0xffffffffu, d0, 2);
        float ex0 = __expf(d0 * SCALE + __ldg(&bias[(size_t)e0 * NHD + h]));
        z += ex0;
        float2 va = __bfloat1622float2(*(bf162*)&v0.x);
        float2 vb = __bfloat1622float2(*(bf162*)&v0.y);
        a0 += ex0 * va.x; a1 += ex0 * va.y;
        a2 += ex0 * vb.x; a3 += ex0 * vb.y;
    }

    float rz = 1.0f / (z + 1e-16f);
    *(float4*)(O + (size_t)orow * HID + lane * 4) =
        make_float4(a0 * rz, a1 * rz, a2 * rz, a3 * rz);
}

// ---------------- host ----------------
extern "C" void kernel_launch(void* const* d_in, const int* in_sizes, int n_in,
                              void* d_out, int out_size)
{
    const float* x_all    = (const float*)d_in[0];
    const float* bias_c2t = (const float*)d_in[1];
    const float* bias_t2c = (const float*)d_in[2];
    const int*   c2t_row  = (const int*)d_in[3];
    const int*   c2t_col  = (const int*)d_in[4];
    const int*   t2c_row  = (const int*)d_in[5];
    const int*   t2c_col  = (const int*)d_in[6];
    const float* ln1_g    = (const float*)d_in[7];
    const float* ln1_b    = (const float*)d_in[8];
    const float* Wq = (const float*)d_in[9];   const float* bq = (const float*)d_in[10];
    const float* Wk = (const float*)d_in[11];  const float* bk = (const float*)d_in[12];
    const float* Wv = (const float*)d_in[13];  const float* bv = (const float*)d_in[14];
    const float* Wo = (const float*)d_in[15];  const float* bo = (const float*)d_in[16];
    const float* ln2_g = (const float*)d_in[17];
    const float* ln2_b = (const float*)d_in[18];
    const float* W1 = (const float*)d_in[19];  const float* b1 = (const float*)d_in[20];
    const float* W2 = (const float*)d_in[21];  const float* b2 = (const float*)d_in[22];
    float* out = (float*)d_out;

    float *o;
    bf16 *qb, *kv;
    int *cnt, *start, *fill, *sorted;
    cudaGetSymbolAddress((void**)&qb, g_qb);
    cudaGetSymbolAddress((void**)&kv, g_kv);
    cudaGetSymbolAddress((void**)&o,  g_o);
    cudaGetSymbolAddress((void**)&cnt,    g_cnt);
    cudaGetSymbolAddress((void**)&start,  g_start);
    cudaGetSymbolAddress((void**)&fill,   g_fill);
    cudaGetSymbolAddress((void**)&sorted, g_sorted);

    cudaFuncSetAttribute(qkv_kernel,
                         cudaFuncAttributeMaxDynamicSharedMemorySize, QKV_SMEM);
    cudaFuncSetAttribute(tail_kernel,
                         cudaFuncAttributeMaxDynamicSharedMemorySize, TAIL_SMEM);

    const int gemmGrid = (NALL + 127) / 128;
    const int eGrid    = (EDG + 255) / 256;
    const int nb       = (NALL + 1023) / 1024;

    // CSR build + weight prep (both independent of qkv)
    cudaMemsetAsync(cnt, 0, (NALL + 1) * sizeof(int), 0);
    hist_kernel<<<eGrid, 256>>>(c2t_row, t2c_row, cnt);
    prep_w_kernel<<<dim3(64, 3), 256>>>(Wq, Wk, Wv);
    scan_kernel<<<nb, 256>>>(cnt, start, fill, NALL);
    scatter_kernel<<<eGrid, 256>>>(c2t_row, t2c_row, fill, sorted);

    // LN1 + QKV (bf16 tensor cores; K/V interleaved)
    qkv_kernel<<<gemmGrid, 256, QKV_SMEM>>>(x_all, ln1_g, ln1_b,
                                            bq, bk, bv, qb, kv, NALL);

    edge_agg_kernel<<<(NALL + 7) / 8, 256>>>(qb, kv, c2t_col, t2c_col,
                                             bias_c2t, bias_t2c,
                                             start, cnt, sorted, o);

    tail_kernel<<<gemmGrid, 256, TAIL_SMEM>>>(o, x_all, Wo, bo, ln2_g, ln2_b,
                                              W1, b1, W2, b2, out, NALL);
}